// round 13
// baseline (speedup 1.0000x reference)
#include <cuda_runtime.h>

#define BB   4
#define CIN  64
#define COUT 64
#define NPTS 8192
#define KNN  16
#define NQ   (BB * NPTS)
#define QPB  64             // queries per collect block
#define KTH  6              // threshold order statistic
#define CAPQ 32             // per-thread (per-quarter) hit buffer
#define QCAND 2048          // candidates per quarter-thread
#define STEPC 512           // candidates per region per step

// Static scratch (no runtime allocation allowed)
__device__ int   g_idx[NQ * KNN];   // [q][k]      2 MB
__device__ float g_z[NQ * COUT];    // zT[b][n][o] 8 MB
__device__ int   g_wcount;          // fallback worklist size
__device__ int   g_wlist[NQ];       // fallback worklist

typedef unsigned long long ull;

// --------------------------- f32x2 helpers ---------------------------------
__device__ __forceinline__ ull pk2(float lo, float hi) {
    ull r; asm("mov.b64 %0, {%1, %2};" : "=l"(r) : "f"(lo), "f"(hi)); return r;
}
__device__ __forceinline__ void upk2(ull v, float& lo, float& hi) {
    asm("mov.b64 {%0, %1}, %2;" : "=f"(lo), "=f"(hi) : "l"(v));
}
__device__ __forceinline__ ull mul2(ull a, ull b) {
    ull r; asm("mul.rn.f32x2 %0, %1, %2;" : "=l"(r) : "l"(a), "l"(b)); return r;
}
__device__ __forceinline__ ull add2(ull a, ull b) {
    ull r; asm("add.rn.f32x2 %0, %1, %2;" : "=l"(r) : "l"(a), "l"(b)); return r;
}
__device__ __forceinline__ ull fma2(ull a, ull b, ull c) {
    ull r; asm("fma.rn.f32x2 %0, %1, %2, %3;" : "=l"(r) : "l"(a), "l"(b), "l"(c)); return r;
}

// Monotone key: (order-preserving uint of d) << 32 | j. Lexicographic (d, j)
// compare == single u64 compare. Works for negative d (sign-flip transform).
__device__ __forceinline__ ull dj_key(float d, int j) {
    unsigned kd = __float_as_uint(d);
    kd ^= ((unsigned)((int)kd >> 31)) | 0x80000000u;
    ull r; asm("mov.b64 %0, {%1, %2};" : "=l"(r) : "r"((unsigned)j), "r"(kd));
    return r;   // low word = j, high word = kd
}

#define KEY_INF 0xFFFFFFFFFFFFFFFFull

// Insert key into ascending 16-slot register list (branch guarded by caller).
#define KQ_INSERT(kq, v_) do {                                                \
    ull v = (v_);                                                             \
    _Pragma("unroll")                                                         \
    for (int s_ = 0; s_ < KNN; s_++) {                                        \
        ull o_ = kq[s_];                                                      \
        bool pr_ = v < o_;                                                    \
        kq[s_] = pr_ ? v : o_;                                                \
        v      = pr_ ? o_ : v;                                                \
    }                                                                         \
} while (0)

// ---------------------------------------------------------------------------
// Collect, 4-way candidate split. 256 threads / 64 queries per block.
// Quarter h of query q scans candidates [h*2048,(h+1)*2048) from plane-
// separated smem tiles. T = 6th smallest of a 1024-point stride-8 subsample
// (cooperative: each quarter scans 256 samples, value-merge of four 6-lists
// -> identical T for all partners). Hits d<=T buffered as u64 keys ->
// per-thread top-16 -> 2-stage tree merge (exact lexicographic set).
// ---------------------------------------------------------------------------
__global__ void __launch_bounds__(256) knn_collect(const float* __restrict__ coords) {
    __shared__ __align__(16) float st[4][2048];   // 32KB, multi-purpose
    __shared__ int scnt[256];

    ull buf[CAPQ];                    // per-thread local (stack)

    int tid = threadIdx.x;            // 0..255
    int ql  = tid & 63;               // query lane
    int h   = tid >> 6;               // quarter 0..3
    int q   = blockIdx.x * QPB + ql;
    int b   = blockIdx.x >> 7;        // 128 blocks per batch
    int n   = q & (NPTS - 1);
    const float* cb = coords + b * 3 * NPTS;

    float qx = cb[n], qy = cb[NPTS + n], qz = cb[2 * NPTS + n];
    float sqi = (qx * qx + qy * qy) + qz * qz;

    // ---- Phase 1: cooperative threshold (6th of 1024-sample) --------------
    float T;
    {
        float4* sp = (float4*)&st[0][0];          // 1024 float4 in st[0..1]
        for (int t = tid; t < 1024; t += 256) {
            int j = t * 8;
            float cx = cb[j], cy = cb[NPTS + j], cz = cb[2 * NPTS + j];
            sp[t] = make_float4(cx, cy, cz, (cx * cx + cy * cy) + cz * cz);
        }
        __syncthreads();

        float t6[KTH];
#pragma unroll
        for (int s = 0; s < KTH; s++) t6[s] = __int_as_float(0x7f800000);
#pragma unroll 4
        for (int tt = 0; tt < 256; tt++) {
            float4 c = sp[h * 256 + tt];
            float inner = fmaf(qz, c.z, fmaf(qy, c.y, qx * c.x));
            float d = fmaf(-2.0f, inner, sqi + c.w);
            if (d < t6[KTH - 1]) {
                float v = d;
#pragma unroll
                for (int s = 0; s < KTH; s++) {
                    float lo = fminf(t6[s], v);
                    float hi = fmaxf(t6[s], v);
                    t6[s] = lo; v = hi;
                }
            }
        }

        float* L6 = &st[2][0];                     // 256*6 floats
#pragma unroll
        for (int s = 0; s < KTH; s++) L6[tid * KTH + s] = t6[s];
        __syncthreads();

#pragma unroll
        for (int k = 1; k < 4; k++) {
            int pt = ql + (((h + k) & 3) << 6);
#pragma unroll
            for (int s = 0; s < KTH; s++) {
                float v = L6[pt * KTH + s];
                if (v < t6[KTH - 1]) {
                    float w = v;
#pragma unroll
                    for (int s2 = 0; s2 < KTH; s2++) {
                        float lo = fminf(t6[s2], w);
                        float hi = fmaxf(t6[s2], w);
                        t6[s2] = lo; w = hi;
                    }
                }
            }
        }
        T = t6[KTH - 1];   // 6th smallest of the 1024-sample union
    }

    // ---- Phase 2: quarter-scan + collect (plane-separated tiles) ----------
    ull qx2 = pk2(qx, qx), qy2 = pk2(qy, qy), qz2 = pk2(qz, qz);
    ull sq2 = pk2(sqi, sqi);
    ull m2  = pk2(-2.0f, -2.0f);

    int cnt = 0;
    for (int step = 0; step < 4; step++) {
        __syncthreads();               // prior readers done (incl. phase 1)
        // Stage: region r = quarter r's 512-candidate window, as 4 planes.
        for (int e = tid; e < 2048; e += 256) {
            int r  = e >> 9;
            int ei = e & 511;
            int j  = r * QCAND + step * STEPC + ei;
            float cx = cb[j], cy = cb[NPTS + j], cz = cb[2 * NPTS + j];
            float* f = st[r];
            f[ei]        = cx;          // coalesced, conflict-free
            f[512 + ei]  = cy;
            f[1024 + ei] = cz;
            f[1536 + ei] = (cx * cx + cy * cy) + cz * cz;
        }
        __syncthreads();

        const float* f = st[h];
        int jbase = h * QCAND + step * STEPC;
#pragma unroll 4
        for (int pp = 0; pp < 128; pp++) {         // 4 candidates per iter
            ulonglong2 X  = *(const ulonglong2*)(f + 4 * pp);
            ulonglong2 Y  = *(const ulonglong2*)(f + 512 + 4 * pp);
            ulonglong2 Z  = *(const ulonglong2*)(f + 1024 + 4 * pp);
            ulonglong2 Wv = *(const ulonglong2*)(f + 1536 + 4 * pp);
            // pair A = candidates 0,1 ; pair B = candidates 2,3
            ull tA = mul2(qx2, X.x);
            tA = fma2(qy2, Y.x, tA);
            tA = fma2(qz2, Z.x, tA);
            ull dA = fma2(m2, tA, add2(sq2, Wv.x));
            ull tB = mul2(qx2, X.y);
            tB = fma2(qy2, Y.y, tB);
            tB = fma2(qz2, Z.y, tB);
            ull dB = fma2(m2, tB, add2(sq2, Wv.y));
            float d0, d1, d2, d3;
            upk2(dA, d0, d1);
            upk2(dB, d2, d3);
            int j0 = jbase + 4 * pp;
            if (fminf(d0, d1) <= T) {
                if (d0 <= T) { if (cnt < CAPQ) buf[cnt] = dj_key(d0, j0);     cnt++; }
                if (d1 <= T) { if (cnt < CAPQ) buf[cnt] = dj_key(d1, j0 + 1); cnt++; }
            }
            if (fminf(d2, d3) <= T) {
                if (d2 <= T) { if (cnt < CAPQ) buf[cnt] = dj_key(d2, j0 + 2); cnt++; }
                if (d3 <= T) { if (cnt < CAPQ) buf[cnt] = dj_key(d3, j0 + 3); cnt++; }
            }
        }
    }

    // ---- per-thread top-16 (u64 keys; order-independent exact set) --------
    ull kq[KNN];
#pragma unroll
    for (int s = 0; s < KNN; s++) kq[s] = KEY_INF;

    int m = cnt < CAPQ ? cnt : CAPQ;
    for (int t = 0; t < m; t++) {
        ull k = buf[t];
        if (k < kq[KNN - 1]) KQ_INSERT(kq, k);
    }

    // ---- publish + 2-stage tree merge --------------------------------------
    __syncthreads();                    // done reading tiles; reuse st
    ull* Lk = (ull*)&st[0][0];          // 256 lists x 16 keys = 32KB exactly
#pragma unroll
    for (int s = 0; s < KNN; s++) Lk[tid * KNN + s] = kq[s];
    scnt[tid] = cnt;
    __syncthreads();

    // Stage 1: h in {0,1} merges partner h+2.
    if (tid < 128) {
        int pt = tid + 128;
#pragma unroll
        for (int s2 = 0; s2 < KNN; s2++) {
            ull k = Lk[pt * KNN + s2];
            if (k < kq[KNN - 1]) KQ_INSERT(kq, k);
        }
        int c2 = scnt[pt];
        int bad = (cnt > CAPQ) | (c2 > CAPQ);
        scnt[tid] = ((cnt + c2) & 0xFFFFFF) | (bad << 24);
#pragma unroll
        for (int s = 0; s < KNN; s++) Lk[tid * KNN + s] = kq[s];
    }
    __syncthreads();

    // Stage 2: h==0 merges partner h==1; owns output.
    if (tid < 64) {
        int pt = tid + 64;
#pragma unroll
        for (int s2 = 0; s2 < KNN; s2++) {
            ull k = Lk[pt * KNN + s2];
            if (k < kq[KNN - 1]) KQ_INSERT(kq, k);
        }
        int a = scnt[tid], c = scnt[pt];
        int total = (a & 0xFFFFFF) + (c & 0xFFFFFF);
        int bad   = ((a | c) >> 24) & 1;

        int* op = g_idx + q * KNN;
#pragma unroll
        for (int s = 0; s < KNN; s++) op[s] = (int)(unsigned)(kq[s] & 0xFFFFFFFFull);

        if (total < KNN || bad) {
            int slot = atomicAdd(&g_wcount, 1);
            g_wlist[slot] = q;
        }
    }
}

// ---------------------------------------------------------------------------
// Fallback: BLOCK-cooperative exact scan (256 threads per flagged query) —
// unchanged (verified R9/R11/R12).
// ---------------------------------------------------------------------------
__global__ void __launch_bounds__(256) knn_fallback(const float* __restrict__ coords) {
    __shared__ float sd[256][KNN];
    __shared__ int   sj[256][KNN];
    __shared__ float md[8 * KNN];
    __shared__ int   mj[8 * KNN];

    int tid  = threadIdx.x;
    int lane = tid & 31;
    int wid  = tid >> 5;
    int nw   = g_wcount;

    for (int w = blockIdx.x; w < nw; w += 64) {
        int q = g_wlist[w];
        int b = q >> 13, n = q & (NPTS - 1);
        const float* cb = coords + b * 3 * NPTS;
        float qx = cb[n], qy = cb[NPTS + n], qz = cb[2 * NPTS + n];
        float sqi = (qx * qx + qy * qy) + qz * qz;

        float ds[KNN];
        int   is_[KNN];
#pragma unroll
        for (int s = 0; s < KNN; s++) { ds[s] = __int_as_float(0x7f800000); is_[s] = 0x7fffffff; }

        for (int i0 = 0; i0 < 32; i0 += 8) {
            float cxs[8], cys[8], czs[8];
#pragma unroll
            for (int u = 0; u < 8; u++) {
                int j = (i0 + u) * 256 + tid;
                cxs[u] = __ldg(cb + j);
                cys[u] = __ldg(cb + NPTS + j);
                czs[u] = __ldg(cb + 2 * NPTS + j);
            }
#pragma unroll
            for (int u = 0; u < 8; u++) {
                int j = (i0 + u) * 256 + tid;
                float sq = (cxs[u] * cxs[u] + cys[u] * cys[u]) + czs[u] * czs[u];
                float inner = fmaf(qz, czs[u], fmaf(qy, cys[u], qx * cxs[u]));
                float d = fmaf(-2.0f, inner, sqi + sq);
                if (d < ds[KNN - 1]) {
                    float vd = d; int vi = j;
#pragma unroll
                    for (int s = 0; s < KNN; s++) {
                        float od = ds[s]; int oi = is_[s];
                        bool  pr = vd < od;
                        ds[s]  = pr ? vd : od;
                        is_[s] = pr ? vi : oi;
                        vd     = pr ? od : vd;
                        vi     = pr ? oi : vi;
                    }
                }
            }
        }

#pragma unroll
        for (int s = 0; s < KNN; s++) { sd[tid][s] = ds[s]; sj[tid][s] = is_[s]; }
        __syncthreads();

        {
            int ptr = 0;
            for (int k = 0; k < KNN; k++) {
                float cd = (ptr < KNN) ? sd[tid][ptr] : __int_as_float(0x7f800000);
                int   cj = (ptr < KNN) ? sj[tid][ptr] : 0x7fffffff;
                float wd = cd; int wj = cj;
#pragma unroll
                for (int off = 16; off > 0; off >>= 1) {
                    float od = __shfl_xor_sync(0xffffffffu, wd, off);
                    int   oj = __shfl_xor_sync(0xffffffffu, wj, off);
                    if (od < wd || (od == wd && oj < wj)) { wd = od; wj = oj; }
                }
                if (wd == cd && wj == cj) ptr++;
                if (lane == 0) { md[wid * KNN + k] = wd; mj[wid * KNN + k] = wj; }
            }
        }
        __syncthreads();

        if (wid == 0) {
            float fd[4]; int fj[4];
            int base = (lane >> 2) * KNN + (lane & 3) * 4;
#pragma unroll
            for (int t = 0; t < 4; t++) { fd[t] = md[base + t]; fj[t] = mj[base + t]; }
            int ptr = 0;
            for (int k = 0; k < KNN; k++) {
                float cd = (ptr < 4) ? fd[ptr] : __int_as_float(0x7f800000);
                int   cj = (ptr < 4) ? fj[ptr] : 0x7fffffff;
                float wd = cd; int wj = cj;
#pragma unroll
                for (int off = 16; off > 0; off >>= 1) {
                    float od = __shfl_xor_sync(0xffffffffu, wd, off);
                    int   oj = __shfl_xor_sync(0xffffffffu, wj, off);
                    if (od < wd || (od == wd && oj < wj)) { wd = od; wj = oj; }
                }
                if (wd == cd && wj == cj) ptr++;
                if (lane == 0) g_idx[q * KNN + k] = wj;
            }
        }
        __syncthreads();
    }
}

// ---------------------------------------------------------------------------
// GEMM: z[b][n][o] = sum_c W[o][c] * x[b][c][n]; zeroes worklist counter.
// ---------------------------------------------------------------------------
__global__ void __launch_bounds__(128) gemm_kernel(const float* __restrict__ x,
                                                   const float* __restrict__ W) {
    if (blockIdx.x == 0 && threadIdx.x == 0) g_wcount = 0;

    __shared__ float ws[COUT * CIN];
    int tid = threadIdx.x;
#pragma unroll
    for (int u = 0; u < 8; u++)
        ((float4*)ws)[tid + u * 128] = ((const float4*)W)[tid + u * 128];
    __syncthreads();

    int b     = blockIdx.x >> 7;
    int ntile = (blockIdx.x & 127) * 64;
    int nl    = tid & 63;
    int o0    = (tid >> 6) * 32;
    int n     = ntile + nl;

    const float* xb = x + b * CIN * NPTS;

    float acc[32];
#pragma unroll
    for (int i = 0; i < 32; i++) acc[i] = 0.0f;

    for (int c = 0; c < CIN; c += 4) {
        float xv0 = xb[(c + 0) * NPTS + n];
        float xv1 = xb[(c + 1) * NPTS + n];
        float xv2 = xb[(c + 2) * NPTS + n];
        float xv3 = xb[(c + 3) * NPTS + n];
#pragma unroll
        for (int i = 0; i < 32; i++) {
            float4 w4 = *(const float4*)&ws[(o0 + i) * CIN + c];
            acc[i] = fmaf(w4.x, xv0, acc[i]);
            acc[i] = fmaf(w4.y, xv1, acc[i]);
            acc[i] = fmaf(w4.z, xv2, acc[i]);
            acc[i] = fmaf(w4.w, xv3, acc[i]);
        }
    }

    float* zp = g_z + ((size_t)b * NPTS + n) * COUT + o0;
#pragma unroll
    for (int i = 0; i < 32; i += 4)
        *(float4*)&zp[i] = make_float4(acc[i], acc[i + 1], acc[i + 2], acc[i + 3]);
}

// ---------------------------------------------------------------------------
// Max-gather + coords passthrough (tail blocks).
// ---------------------------------------------------------------------------
#define MG_BLOCKS   (BB * 256)
#define CP_FLOAT4   (BB * 3 * NPTS / 4)
#define CP_BLOCKS   (CP_FLOAT4 / 256)

__global__ void __launch_bounds__(256) maxgather_kernel(float* __restrict__ y,
                                                        const float* __restrict__ coords) {
    if (blockIdx.x >= MG_BLOCKS) {
        int i = (blockIdx.x - MG_BLOCKS) * 256 + threadIdx.x;
        float4* dst = (float4*)(y + (size_t)BB * COUT * NPTS);
        dst[i] = ((const float4*)coords)[i];
        return;
    }

    __shared__ float yt[COUT][33];

    int tid = threadIdx.x;
    int w   = tid >> 5;
    int l   = tid & 31;
    int b     = blockIdx.x >> 8;
    int ntile = (blockIdx.x & 255) * 32;

    const float* zb = g_z + (size_t)b * NPTS * COUT;
    const float NEG_INF = __int_as_float(0xff800000);

    for (int qq = 0; qq < 4; qq++) {
        int nl = w * 4 + qq;
        int n  = ntile + nl;
        const int* ip = g_idx + ((size_t)b * NPTS + n) * KNN;
        float m0 = NEG_INF, m1 = NEG_INF;
#pragma unroll
        for (int k = 0; k < KNN; k++) {
            int r = __ldg(&ip[k]);
            const float* zr = zb + (size_t)r * COUT;
            m0 = fmaxf(m0, zr[l]);
            m1 = fmaxf(m1, zr[l + 32]);
        }
        yt[l][nl]      = m0;
        yt[l + 32][nl] = m1;
    }
    __syncthreads();

#pragma unroll
    for (int e = tid; e < COUT * 32; e += 256) {
        int o  = e >> 5;
        int nl = e & 31;
        y[((size_t)b * COUT + o) * NPTS + ntile + nl] = yt[o][nl];
    }
}

// ---------------------------------------------------------------------------
extern "C" void kernel_launch(void* const* d_in, const int* in_sizes, int n_in,
                              void* d_out, int out_size) {
    const float* x      = (const float*)d_in[0];
    const float* coords = (const float*)d_in[1];
    const float* W      = (const float*)d_in[2];
    float*       out    = (float*)d_out;

    gemm_kernel<<<BB * 128, 128>>>(x, W);
    knn_collect<<<NQ / QPB, 256>>>(coords);
    knn_fallback<<<64, 256>>>(coords);
    maxgather_kernel<<<MG_BLOCKS + CP_BLOCKS, 256>>>(out, coords);
}

// round 14
// speedup vs baseline: 1.1800x; 1.1800x over previous
#include <cuda_runtime.h>

#define BB   4
#define CIN  64
#define COUT 64
#define NPTS 8192
#define KNN  16
#define NQ   (BB * NPTS)
#define QPB  64             // queries per collect block
#define KTH  6              // threshold order statistic (R14: 8 -> 6)
#define CAPQ 40             // per-thread (per-quarter) hit buffer
#define QCAND 2048          // candidates per quarter-thread
#define STEPC 512           // candidates per region per step

// Static scratch (no runtime allocation allowed)
__device__ int   g_idx[NQ * KNN];   // [q][k]      2 MB
__device__ float g_z[NQ * COUT];    // zT[b][n][o] 8 MB
__device__ int   g_wcount;          // fallback worklist size
__device__ int   g_wlist[NQ];       // fallback worklist

// --------------------------- f32x2 helpers ---------------------------------
__device__ __forceinline__ unsigned long long pk2(float lo, float hi) {
    unsigned long long r;
    asm("mov.b64 %0, {%1, %2};" : "=l"(r) : "f"(lo), "f"(hi));
    return r;
}
__device__ __forceinline__ void upk2(unsigned long long v, float& lo, float& hi) {
    asm("mov.b64 {%0, %1}, %2;" : "=f"(lo), "=f"(hi) : "l"(v));
}
__device__ __forceinline__ unsigned long long mul2(unsigned long long a, unsigned long long b) {
    unsigned long long r;
    asm("mul.rn.f32x2 %0, %1, %2;" : "=l"(r) : "l"(a), "l"(b));
    return r;
}
__device__ __forceinline__ unsigned long long add2(unsigned long long a, unsigned long long b) {
    unsigned long long r;
    asm("add.rn.f32x2 %0, %1, %2;" : "=l"(r) : "l"(a), "l"(b));
    return r;
}
__device__ __forceinline__ unsigned long long fma2(unsigned long long a, unsigned long long b,
                                                   unsigned long long c) {
    unsigned long long r;
    asm("fma.rn.f32x2 %0, %1, %2, %3;" : "=l"(r) : "l"(a), "l"(b), "l"(c));
    return r;
}

// ---------------------------------------------------------------------------
// Collect, 4-way candidate split (R12 structure, KTH=6): 256 threads, 64
// queries per block (512 blocks). Threads (ql, ql+64, ql+128, ql+192) share
// query q; quarter h scans candidates [h*2048, (h+1)*2048) via smem tiles.
// T = 6th smallest of a 1024-point stride-8 subsample, computed
// cooperatively (value merge -> identical T for all partners). Hits d<=T ->
// 40-entry local buffer -> per-thread sorted top-16 -> owner (h==0) merges
// partners in quarter order (exact top_k tie-break). Rare bad queries ->
// fallback worklist.
// ---------------------------------------------------------------------------
__global__ void __launch_bounds__(256) knn_collect(const float* __restrict__ coords) {
    __shared__ __align__(16) float st[4][2048];   // 32KB, multi-purpose
    __shared__ int scnt[256];

    unsigned long long buf[CAPQ];     // per-thread local (stack)

    int tid = threadIdx.x;            // 0..255
    int ql  = tid & 63;               // query lane
    int h   = tid >> 6;               // quarter: 0..3
    int q   = blockIdx.x * QPB + ql;
    int b   = blockIdx.x >> 7;        // 128 blocks per batch
    int n   = q & (NPTS - 1);
    const float* cb = coords + b * 3 * NPTS;

    float qx = cb[n], qy = cb[NPTS + n], qz = cb[2 * NPTS + n];
    float sqi = (qx * qx + qy * qy) + qz * qz;

    // ---- Phase 1: cooperative threshold (6th of 1024-sample) --------------
    float T;
    {
        float4* sp = (float4*)&st[0][0];   // 1024 float4 = 16KB (st[0..1])
        for (int t = tid; t < 1024; t += 256) {
            int j = t * 8;
            float cx = cb[j], cy = cb[NPTS + j], cz = cb[2 * NPTS + j];
            sp[t] = make_float4(cx, cy, cz, (cx * cx + cy * cy) + cz * cz);
        }
        __syncthreads();

        float t6[KTH];
#pragma unroll
        for (int s = 0; s < KTH; s++) t6[s] = __int_as_float(0x7f800000);
#pragma unroll 4
        for (int tt = 0; tt < 256; tt++) {
            float4 c = sp[h * 256 + tt];
            float inner = fmaf(qz, c.z, fmaf(qy, c.y, qx * c.x));
            float d = fmaf(-2.0f, inner, sqi + c.w);
            if (d < t6[KTH - 1]) {
                float v = d;
#pragma unroll
                for (int s = 0; s < KTH; s++) {
                    float lo = fminf(t6[s], v);
                    float hi = fmaxf(t6[s], v);
                    t6[s] = lo; v = hi;
                }
            }
        }

        // Publish the four sorted 6-lists (6KB, in st[2]) and merge values.
        float* L6 = &st[2][0];
#pragma unroll
        for (int s = 0; s < KTH; s++) L6[tid * KTH + s] = t6[s];
        __syncthreads();

#pragma unroll
        for (int k = 1; k < 4; k++) {
            int pt = ql + (((h + k) & 3) << 6);
#pragma unroll
            for (int s = 0; s < KTH; s++) {
                float v = L6[pt * KTH + s];
                if (v < t6[KTH - 1]) {
                    float w = v;
#pragma unroll
                    for (int s2 = 0; s2 < KTH; s2++) {
                        float lo = fminf(t6[s2], w);
                        float hi = fmaxf(t6[s2], w);
                        t6[s2] = lo; w = hi;
                    }
                }
            }
        }
        T = t6[KTH - 1];    // 6th smallest value of the 1024-sample union
    }

    // ---- Phase 2: quarter-scan + collect ----------------------------------
    unsigned long long qx2 = pk2(qx, qx), qy2 = pk2(qy, qy), qz2 = pk2(qz, qz);
    unsigned long long sq2 = pk2(sqi, sqi);
    unsigned long long m2  = pk2(-2.0f, -2.0f);

    int cnt = 0;
    for (int step = 0; step < 4; step++) {
        __syncthreads();               // prior readers done
        // Stage: region r holds quarter r's current 512-candidate window.
        for (int e = tid; e < 2048; e += 256) {
            int r  = e >> 9;
            int ei = e & 511;
            int j  = r * QCAND + step * STEPC + ei;
            float cx = cb[j], cy = cb[NPTS + j], cz = cb[2 * NPTS + j];
            float* f = st[r];
            int p = ei >> 1, o = ei & 1;
            f[p * 8 + o]     = cx;
            f[p * 8 + 2 + o] = cy;
            f[p * 8 + 4 + o] = cz;
            f[p * 8 + 6 + o] = (cx * cx + cy * cy) + cz * cz;
        }
        __syncthreads();

        const float* f = st[h];
        int jbase = h * QCAND + step * STEPC;
#pragma unroll 8
        for (int p = 0; p < 256; p++) {
            ulonglong2 a = *(const ulonglong2*)(f + p * 8);      // x01, y01
            ulonglong2 c = *(const ulonglong2*)(f + p * 8 + 4);  // z01, w01
            unsigned long long t0 = mul2(qx2, a.x);
            t0 = fma2(qy2, a.y, t0);
            t0 = fma2(qz2, c.x, t0);
            unsigned long long d2 = fma2(m2, t0, add2(sq2, c.y));
            float d0, d1;
            upk2(d2, d0, d1);
            if (fminf(d0, d1) <= T) {
                int j0 = jbase + 2 * p;
                if (d0 <= T) {
                    if (cnt < CAPQ)
                        buf[cnt] = ((unsigned long long)(unsigned)j0 << 32) | __float_as_uint(d0);
                    cnt++;
                }
                if (d1 <= T) {
                    if (cnt < CAPQ)
                        buf[cnt] = ((unsigned long long)(unsigned)(j0 + 1) << 32) | __float_as_uint(d1);
                    cnt++;
                }
            }
        }
    }

    // ---- per-thread sorted top-16 from buffer -----------------------------
    float ds[KNN];
    int   is_[KNN];
#pragma unroll
    for (int s = 0; s < KNN; s++) { ds[s] = __int_as_float(0x7f800000); is_[s] = 0; }

    int m = cnt < CAPQ ? cnt : CAPQ;
    for (int t = 0; t < m; t++) {
        unsigned long long e = buf[t];
        float d = __uint_as_float((unsigned)e);
        int   j = (int)(e >> 32);
        if (d < ds[KNN - 1]) {
            float vd = d; int vi = j;
#pragma unroll
            for (int s = 0; s < KNN; s++) {
                float od = ds[s]; int oi = is_[s];
                bool  pr = vd < od;
                ds[s]  = pr ? vd : od;
                is_[s] = pr ? vi : oi;
                vd     = pr ? od : vd;
                vi     = pr ? oi : vi;
            }
        }
    }

    // ---- publish lists + counts, merge (quarter 0 owns the query) ---------
    __syncthreads();                   // done reading tiles; reuse st
    float* Ld = (float*)&st[0][0];             // [256][16] floats, 16KB
    int*   Lj = (int*)&st[0][0] + 256 * KNN;   // [256][16] ints,   16KB
#pragma unroll
    for (int s = 0; s < KNN; s++) { Ld[tid * KNN + s] = ds[s]; Lj[tid * KNN + s] = is_[s]; }
    scnt[tid] = cnt;
    __syncthreads();

    if (h == 0) {
        int bad = (cnt > CAPQ);
        int total = cnt;
        // Insert partners in quarter order 1,2,3 (their j ranges ascend), so
        // the strict-less bubble reproduces top_k's lowest-index tie-break.
#pragma unroll
        for (int k = 1; k < 4; k++) {
            int pt = ql + (k << 6);
            int ck = scnt[pt];
            total += ck;
            bad |= (ck > CAPQ);
#pragma unroll
            for (int s2 = 0; s2 < KNN; s2++) {
                float d = Ld[pt * KNN + s2];
                int   j = Lj[pt * KNN + s2];
                if (d < ds[KNN - 1]) {
                    float vd = d; int vi = j;
#pragma unroll
                    for (int s = 0; s < KNN; s++) {
                        float od = ds[s]; int oi = is_[s];
                        bool  pr = vd < od;
                        ds[s]  = pr ? vd : od;
                        is_[s] = pr ? vi : oi;
                        vd     = pr ? od : vd;
                        vi     = pr ? oi : vi;
                    }
                }
            }
        }

        int* op = g_idx + q * KNN;
#pragma unroll
        for (int s = 0; s < KNN; s++) op[s] = is_[s];

        if (total < KNN || bad) {
            int slot = atomicAdd(&g_wcount, 1);
            g_wlist[slot] = q;
        }
    }
}

// ---------------------------------------------------------------------------
// Fallback: BLOCK-cooperative exact scan (256 threads per flagged query) —
// unchanged (verified R9/R11/R12).
// ---------------------------------------------------------------------------
__global__ void __launch_bounds__(256) knn_fallback(const float* __restrict__ coords) {
    __shared__ float sd[256][KNN];
    __shared__ int   sj[256][KNN];
    __shared__ float md[8 * KNN];
    __shared__ int   mj[8 * KNN];

    int tid  = threadIdx.x;
    int lane = tid & 31;
    int wid  = tid >> 5;
    int nw   = g_wcount;

    for (int w = blockIdx.x; w < nw; w += 64) {
        int q = g_wlist[w];
        int b = q >> 13, n = q & (NPTS - 1);
        const float* cb = coords + b * 3 * NPTS;
        float qx = cb[n], qy = cb[NPTS + n], qz = cb[2 * NPTS + n];
        float sqi = (qx * qx + qy * qy) + qz * qz;

        float ds[KNN];
        int   is_[KNN];
#pragma unroll
        for (int s = 0; s < KNN; s++) { ds[s] = __int_as_float(0x7f800000); is_[s] = 0x7fffffff; }

        for (int i0 = 0; i0 < 32; i0 += 8) {
            float cxs[8], cys[8], czs[8];
#pragma unroll
            for (int u = 0; u < 8; u++) {
                int j = (i0 + u) * 256 + tid;
                cxs[u] = __ldg(cb + j);
                cys[u] = __ldg(cb + NPTS + j);
                czs[u] = __ldg(cb + 2 * NPTS + j);
            }
#pragma unroll
            for (int u = 0; u < 8; u++) {
                int j = (i0 + u) * 256 + tid;
                float sq = (cxs[u] * cxs[u] + cys[u] * cys[u]) + czs[u] * czs[u];
                float inner = fmaf(qz, czs[u], fmaf(qy, cys[u], qx * cxs[u]));
                float d = fmaf(-2.0f, inner, sqi + sq);
                if (d < ds[KNN - 1]) {
                    float vd = d; int vi = j;
#pragma unroll
                    for (int s = 0; s < KNN; s++) {
                        float od = ds[s]; int oi = is_[s];
                        bool  pr = vd < od;
                        ds[s]  = pr ? vd : od;
                        is_[s] = pr ? vi : oi;
                        vd     = pr ? od : vd;
                        vi     = pr ? oi : vi;
                    }
                }
            }
        }

#pragma unroll
        for (int s = 0; s < KNN; s++) { sd[tid][s] = ds[s]; sj[tid][s] = is_[s]; }
        __syncthreads();

        {
            int ptr = 0;
            for (int k = 0; k < KNN; k++) {
                float cd = (ptr < KNN) ? sd[tid][ptr] : __int_as_float(0x7f800000);
                int   cj = (ptr < KNN) ? sj[tid][ptr] : 0x7fffffff;
                float wd = cd; int wj = cj;
#pragma unroll
                for (int off = 16; off > 0; off >>= 1) {
                    float od = __shfl_xor_sync(0xffffffffu, wd, off);
                    int   oj = __shfl_xor_sync(0xffffffffu, wj, off);
                    if (od < wd || (od == wd && oj < wj)) { wd = od; wj = oj; }
                }
                if (wd == cd && wj == cj) ptr++;
                if (lane == 0) { md[wid * KNN + k] = wd; mj[wid * KNN + k] = wj; }
            }
        }
        __syncthreads();

        if (wid == 0) {
            float fd[4]; int fj[4];
            int base = (lane >> 2) * KNN + (lane & 3) * 4;
#pragma unroll
            for (int t = 0; t < 4; t++) { fd[t] = md[base + t]; fj[t] = mj[base + t]; }
            int ptr = 0;
            for (int k = 0; k < KNN; k++) {
                float cd = (ptr < 4) ? fd[ptr] : __int_as_float(0x7f800000);
                int   cj = (ptr < 4) ? fj[ptr] : 0x7fffffff;
                float wd = cd; int wj = cj;
#pragma unroll
                for (int off = 16; off > 0; off >>= 1) {
                    float od = __shfl_xor_sync(0xffffffffu, wd, off);
                    int   oj = __shfl_xor_sync(0xffffffffu, wj, off);
                    if (od < wd || (od == wd && oj < wj)) { wd = od; wj = oj; }
                }
                if (wd == cd && wj == cj) ptr++;
                if (lane == 0) g_idx[q * KNN + k] = wj;
            }
        }
        __syncthreads();
    }
}

// ---------------------------------------------------------------------------
// GEMM: z[b][n][o] = sum_c W[o][c] * x[b][c][n]; zeroes worklist counter.
// ---------------------------------------------------------------------------
__global__ void __launch_bounds__(128) gemm_kernel(const float* __restrict__ x,
                                                   const float* __restrict__ W) {
    if (blockIdx.x == 0 && threadIdx.x == 0) g_wcount = 0;

    __shared__ float ws[COUT * CIN];
    int tid = threadIdx.x;
#pragma unroll
    for (int u = 0; u < 8; u++)
        ((float4*)ws)[tid + u * 128] = ((const float4*)W)[tid + u * 128];
    __syncthreads();

    int b     = blockIdx.x >> 7;
    int ntile = (blockIdx.x & 127) * 64;
    int nl    = tid & 63;
    int o0    = (tid >> 6) * 32;
    int n     = ntile + nl;

    const float* xb = x + b * CIN * NPTS;

    float acc[32];
#pragma unroll
    for (int i = 0; i < 32; i++) acc[i] = 0.0f;

    for (int c = 0; c < CIN; c += 4) {
        float xv0 = xb[(c + 0) * NPTS + n];
        float xv1 = xb[(c + 1) * NPTS + n];
        float xv2 = xb[(c + 2) * NPTS + n];
        float xv3 = xb[(c + 3) * NPTS + n];
#pragma unroll
        for (int i = 0; i < 32; i++) {
            float4 w4 = *(const float4*)&ws[(o0 + i) * CIN + c];
            acc[i] = fmaf(w4.x, xv0, acc[i]);
            acc[i] = fmaf(w4.y, xv1, acc[i]);
            acc[i] = fmaf(w4.z, xv2, acc[i]);
            acc[i] = fmaf(w4.w, xv3, acc[i]);
        }
    }

    float* zp = g_z + ((size_t)b * NPTS + n) * COUT + o0;
#pragma unroll
    for (int i = 0; i < 32; i += 4)
        *(float4*)&zp[i] = make_float4(acc[i], acc[i + 1], acc[i + 2], acc[i + 3]);
}

// ---------------------------------------------------------------------------
// Max-gather + coords passthrough (tail blocks).
// ---------------------------------------------------------------------------
#define MG_BLOCKS   (BB * 256)
#define CP_FLOAT4   (BB * 3 * NPTS / 4)
#define CP_BLOCKS   (CP_FLOAT4 / 256)

__global__ void __launch_bounds__(256) maxgather_kernel(float* __restrict__ y,
                                                        const float* __restrict__ coords) {
    if (blockIdx.x >= MG_BLOCKS) {
        int i = (blockIdx.x - MG_BLOCKS) * 256 + threadIdx.x;
        float4* dst = (float4*)(y + (size_t)BB * COUT * NPTS);
        dst[i] = ((const float4*)coords)[i];
        return;
    }

    __shared__ float yt[COUT][33];

    int tid = threadIdx.x;
    int w   = tid >> 5;
    int l   = tid & 31;
    int b     = blockIdx.x >> 8;
    int ntile = (blockIdx.x & 255) * 32;

    const float* zb = g_z + (size_t)b * NPTS * COUT;
    const float NEG_INF = __int_as_float(0xff800000);

    for (int qq = 0; qq < 4; qq++) {
        int nl = w * 4 + qq;
        int n  = ntile + nl;
        const int* ip = g_idx + ((size_t)b * NPTS + n) * KNN;
        float m0 = NEG_INF, m1 = NEG_INF;
#pragma unroll
        for (int k = 0; k < KNN; k++) {
            int r = __ldg(&ip[k]);
            const float* zr = zb + (size_t)r * COUT;
            m0 = fmaxf(m0, zr[l]);
            m1 = fmaxf(m1, zr[l + 32]);
        }
        yt[l][nl]      = m0;
        yt[l + 32][nl] = m1;
    }
    __syncthreads();

#pragma unroll
    for (int e = tid; e < COUT * 32; e += 256) {
        int o  = e >> 5;
        int nl = e & 31;
        y[((size_t)b * COUT + o) * NPTS + ntile + nl] = yt[o][nl];
    }
}

// ---------------------------------------------------------------------------
extern "C" void kernel_launch(void* const* d_in, const int* in_sizes, int n_in,
                              void* d_out, int out_size) {
    const float* x      = (const float*)d_in[0];
    const float* coords = (const float*)d_in[1];
    const float* W      = (const float*)d_in[2];
    float*       out    = (float*)d_out;

    gemm_kernel<<<BB * 128, 128>>>(x, W);
    knn_collect<<<NQ / QPB, 256>>>(coords);
    knn_fallback<<<64, 256>>>(coords);
    maxgather_kernel<<<MG_BLOCKS + CP_BLOCKS, 256>>>(out, coords);
}

// round 15
// speedup vs baseline: 1.3281x; 1.1255x over previous
#include <cuda_runtime.h>

#define BB   4
#define CIN  64
#define COUT 64
#define NPTS 8192
#define KNN  16
#define NQ   (BB * NPTS)
#define QPB  64             // queries per collect block
#define KTH  8              // threshold order statistic (locked: 6 regressed)
#define CAPQ 48             // per-thread (per-quarter) hit buffer
#define QCAND 2048          // candidates per quarter-thread
#define STEPC 512           // candidates per region per step

// Static scratch (no runtime allocation allowed)
__device__ int   g_idx[NQ * KNN];   // [q][k]      2 MB
__device__ float g_z[NQ * COUT];    // zT[b][n][o] 8 MB
__device__ int   g_wcount;          // fallback worklist size
__device__ int   g_wlist[NQ];       // fallback worklist

// --------------------------- f32x2 helpers ---------------------------------
__device__ __forceinline__ unsigned long long pk2(float lo, float hi) {
    unsigned long long r;
    asm("mov.b64 %0, {%1, %2};" : "=l"(r) : "f"(lo), "f"(hi));
    return r;
}
__device__ __forceinline__ void upk2(unsigned long long v, float& lo, float& hi) {
    asm("mov.b64 {%0, %1}, %2;" : "=f"(lo), "=f"(hi) : "l"(v));
}
__device__ __forceinline__ unsigned long long mul2(unsigned long long a, unsigned long long b) {
    unsigned long long r;
    asm("mul.rn.f32x2 %0, %1, %2;" : "=l"(r) : "l"(a), "l"(b));
    return r;
}
__device__ __forceinline__ unsigned long long add2(unsigned long long a, unsigned long long b) {
    unsigned long long r;
    asm("add.rn.f32x2 %0, %1, %2;" : "=l"(r) : "l"(a), "l"(b));
    return r;
}
__device__ __forceinline__ unsigned long long fma2(unsigned long long a, unsigned long long b,
                                                   unsigned long long c) {
    unsigned long long r;
    asm("fma.rn.f32x2 %0, %1, %2, %3;" : "=l"(r) : "l"(a), "l"(b), "l"(c));
    return r;
}

// ---------------------------------------------------------------------------
// Collect, 4-way candidate split (R12 configuration): 256 threads, 64
// queries per block (512 blocks). Threads (ql, ql+64, ql+128, ql+192) share
// query q; quarter h scans candidates [h*2048, (h+1)*2048) via smem tiles.
// T = 8th smallest of a 1024-point stride-8 subsample, computed
// cooperatively (value merge -> identical T for all partners). Hits d<=T ->
// 48-entry local buffer -> per-thread sorted top-16 -> owner (h==0) merges
// partners in quarter order (exact top_k tie-break). Rare bad queries ->
// fallback worklist.
// ---------------------------------------------------------------------------
__global__ void __launch_bounds__(256) knn_collect(const float* __restrict__ coords) {
    __shared__ __align__(16) float st[4][2048];   // 32KB, multi-purpose
    __shared__ int scnt[256];

    unsigned long long buf[CAPQ];     // per-thread local (stack)

    int tid = threadIdx.x;            // 0..255
    int ql  = tid & 63;               // query lane
    int h   = tid >> 6;               // quarter: 0..3
    int q   = blockIdx.x * QPB + ql;
    int b   = blockIdx.x >> 7;        // 128 blocks per batch
    int n   = q & (NPTS - 1);
    const float* cb = coords + b * 3 * NPTS;

    float qx = cb[n], qy = cb[NPTS + n], qz = cb[2 * NPTS + n];
    float sqi = (qx * qx + qy * qy) + qz * qz;

    // ---- Phase 1: cooperative threshold (8th of 1024-sample) --------------
    float T;
    {
        float4* sp = (float4*)&st[0][0];   // 1024 float4 = 16KB (st[0..1])
        for (int t = tid; t < 1024; t += 256) {
            int j = t * 8;
            float cx = cb[j], cy = cb[NPTS + j], cz = cb[2 * NPTS + j];
            sp[t] = make_float4(cx, cy, cz, (cx * cx + cy * cy) + cz * cz);
        }
        __syncthreads();

        float t8[KTH];
#pragma unroll
        for (int s = 0; s < KTH; s++) t8[s] = __int_as_float(0x7f800000);
#pragma unroll 4
        for (int tt = 0; tt < 256; tt++) {
            float4 c = sp[h * 256 + tt];
            float inner = fmaf(qz, c.z, fmaf(qy, c.y, qx * c.x));
            float d = fmaf(-2.0f, inner, sqi + c.w);
            if (d < t8[KTH - 1]) {
                float v = d;
#pragma unroll
                for (int s = 0; s < KTH; s++) {
                    float lo = fminf(t8[s], v);
                    float hi = fmaxf(t8[s], v);
                    t8[s] = lo; v = hi;
                }
            }
        }

        // Publish the four sorted 8-lists (8KB, in st[2]) and merge values.
        float* L8 = &st[2][0];
#pragma unroll
        for (int s = 0; s < KTH; s++) L8[tid * KTH + s] = t8[s];
        __syncthreads();

#pragma unroll
        for (int k = 1; k < 4; k++) {
            int pt = ql + (((h + k) & 3) << 6);
#pragma unroll
            for (int s = 0; s < KTH; s++) {
                float v = L8[pt * KTH + s];
                if (v < t8[KTH - 1]) {
                    float w = v;
#pragma unroll
                    for (int s2 = 0; s2 < KTH; s2++) {
                        float lo = fminf(t8[s2], w);
                        float hi = fmaxf(t8[s2], w);
                        t8[s2] = lo; w = hi;
                    }
                }
            }
        }
        T = t8[KTH - 1];    // 8th smallest value of the 1024-sample union
    }

    // ---- Phase 2: quarter-scan + collect ----------------------------------
    unsigned long long qx2 = pk2(qx, qx), qy2 = pk2(qy, qy), qz2 = pk2(qz, qz);
    unsigned long long sq2 = pk2(sqi, sqi);
    unsigned long long m2  = pk2(-2.0f, -2.0f);

    int cnt = 0;
    for (int step = 0; step < 4; step++) {
        __syncthreads();               // prior readers done
        // Stage: region r holds quarter r's current 512-candidate window.
        for (int e = tid; e < 2048; e += 256) {
            int r  = e >> 9;
            int ei = e & 511;
            int j  = r * QCAND + step * STEPC + ei;
            float cx = cb[j], cy = cb[NPTS + j], cz = cb[2 * NPTS + j];
            float* f = st[r];
            int p = ei >> 1, o = ei & 1;
            f[p * 8 + o]     = cx;
            f[p * 8 + 2 + o] = cy;
            f[p * 8 + 4 + o] = cz;
            f[p * 8 + 6 + o] = (cx * cx + cy * cy) + cz * cz;
        }
        __syncthreads();

        const float* f = st[h];
        int jbase = h * QCAND + step * STEPC;
#pragma unroll 8
        for (int p = 0; p < 256; p++) {
            ulonglong2 a = *(const ulonglong2*)(f + p * 8);      // x01, y01
            ulonglong2 c = *(const ulonglong2*)(f + p * 8 + 4);  // z01, w01
            unsigned long long t0 = mul2(qx2, a.x);
            t0 = fma2(qy2, a.y, t0);
            t0 = fma2(qz2, c.x, t0);
            unsigned long long d2 = fma2(m2, t0, add2(sq2, c.y));
            float d0, d1;
            upk2(d2, d0, d1);
            if (fminf(d0, d1) <= T) {
                int j0 = jbase + 2 * p;
                if (d0 <= T) {
                    if (cnt < CAPQ)
                        buf[cnt] = ((unsigned long long)(unsigned)j0 << 32) | __float_as_uint(d0);
                    cnt++;
                }
                if (d1 <= T) {
                    if (cnt < CAPQ)
                        buf[cnt] = ((unsigned long long)(unsigned)(j0 + 1) << 32) | __float_as_uint(d1);
                    cnt++;
                }
            }
        }
    }

    // ---- per-thread sorted top-16 from buffer -----------------------------
    float ds[KNN];
    int   is_[KNN];
#pragma unroll
    for (int s = 0; s < KNN; s++) { ds[s] = __int_as_float(0x7f800000); is_[s] = 0; }

    int m = cnt < CAPQ ? cnt : CAPQ;
    for (int t = 0; t < m; t++) {
        unsigned long long e = buf[t];
        float d = __uint_as_float((unsigned)e);
        int   j = (int)(e >> 32);
        if (d < ds[KNN - 1]) {
            float vd = d; int vi = j;
#pragma unroll
            for (int s = 0; s < KNN; s++) {
                float od = ds[s]; int oi = is_[s];
                bool  pr = vd < od;
                ds[s]  = pr ? vd : od;
                is_[s] = pr ? vi : oi;
                vd     = pr ? od : vd;
                vi     = pr ? oi : vi;
            }
        }
    }

    // ---- publish lists + counts, merge (quarter 0 owns the query) ---------
    __syncthreads();                   // done reading tiles; reuse st
    float* Ld = (float*)&st[0][0];             // [256][16] floats, 16KB
    int*   Lj = (int*)&st[0][0] + 256 * KNN;   // [256][16] ints,   16KB
#pragma unroll
    for (int s = 0; s < KNN; s++) { Ld[tid * KNN + s] = ds[s]; Lj[tid * KNN + s] = is_[s]; }
    scnt[tid] = cnt;
    __syncthreads();

    if (h == 0) {
        int bad = (cnt > CAPQ);
        int total = cnt;
        // Insert partners in quarter order 1,2,3 (their j ranges ascend), so
        // the strict-less bubble reproduces top_k's lowest-index tie-break.
#pragma unroll
        for (int k = 1; k < 4; k++) {
            int pt = ql + (k << 6);
            int ck = scnt[pt];
            total += ck;
            bad |= (ck > CAPQ);
#pragma unroll
            for (int s2 = 0; s2 < KNN; s2++) {
                float d = Ld[pt * KNN + s2];
                int   j = Lj[pt * KNN + s2];
                if (d < ds[KNN - 1]) {
                    float vd = d; int vi = j;
#pragma unroll
                    for (int s = 0; s < KNN; s++) {
                        float od = ds[s]; int oi = is_[s];
                        bool  pr = vd < od;
                        ds[s]  = pr ? vd : od;
                        is_[s] = pr ? vi : oi;
                        vd     = pr ? od : vd;
                        vi     = pr ? oi : vi;
                    }
                }
            }
        }

        int* op = g_idx + q * KNN;
#pragma unroll
        for (int s = 0; s < KNN; s++) op[s] = is_[s];

        if (total < KNN || bad) {
            int slot = atomicAdd(&g_wcount, 1);
            g_wlist[slot] = q;
        }
    }
}

// ---------------------------------------------------------------------------
// Fallback: BLOCK-cooperative exact scan (256 threads per flagged query) —
// unchanged (verified R9/R11/R12/R14).
// ---------------------------------------------------------------------------
__global__ void __launch_bounds__(256) knn_fallback(const float* __restrict__ coords) {
    __shared__ float sd[256][KNN];
    __shared__ int   sj[256][KNN];
    __shared__ float md[8 * KNN];
    __shared__ int   mj[8 * KNN];

    int tid  = threadIdx.x;
    int lane = tid & 31;
    int wid  = tid >> 5;
    int nw   = g_wcount;

    for (int w = blockIdx.x; w < nw; w += 64) {
        int q = g_wlist[w];
        int b = q >> 13, n = q & (NPTS - 1);
        const float* cb = coords + b * 3 * NPTS;
        float qx = cb[n], qy = cb[NPTS + n], qz = cb[2 * NPTS + n];
        float sqi = (qx * qx + qy * qy) + qz * qz;

        float ds[KNN];
        int   is_[KNN];
#pragma unroll
        for (int s = 0; s < KNN; s++) { ds[s] = __int_as_float(0x7f800000); is_[s] = 0x7fffffff; }

        for (int i0 = 0; i0 < 32; i0 += 8) {
            float cxs[8], cys[8], czs[8];
#pragma unroll
            for (int u = 0; u < 8; u++) {
                int j = (i0 + u) * 256 + tid;
                cxs[u] = __ldg(cb + j);
                cys[u] = __ldg(cb + NPTS + j);
                czs[u] = __ldg(cb + 2 * NPTS + j);
            }
#pragma unroll
            for (int u = 0; u < 8; u++) {
                int j = (i0 + u) * 256 + tid;
                float sq = (cxs[u] * cxs[u] + cys[u] * cys[u]) + czs[u] * czs[u];
                float inner = fmaf(qz, czs[u], fmaf(qy, cys[u], qx * cxs[u]));
                float d = fmaf(-2.0f, inner, sqi + sq);
                if (d < ds[KNN - 1]) {
                    float vd = d; int vi = j;
#pragma unroll
                    for (int s = 0; s < KNN; s++) {
                        float od = ds[s]; int oi = is_[s];
                        bool  pr = vd < od;
                        ds[s]  = pr ? vd : od;
                        is_[s] = pr ? vi : oi;
                        vd     = pr ? od : vd;
                        vi     = pr ? oi : vi;
                    }
                }
            }
        }

#pragma unroll
        for (int s = 0; s < KNN; s++) { sd[tid][s] = ds[s]; sj[tid][s] = is_[s]; }
        __syncthreads();

        {
            int ptr = 0;
            for (int k = 0; k < KNN; k++) {
                float cd = (ptr < KNN) ? sd[tid][ptr] : __int_as_float(0x7f800000);
                int   cj = (ptr < KNN) ? sj[tid][ptr] : 0x7fffffff;
                float wd = cd; int wj = cj;
#pragma unroll
                for (int off = 16; off > 0; off >>= 1) {
                    float od = __shfl_xor_sync(0xffffffffu, wd, off);
                    int   oj = __shfl_xor_sync(0xffffffffu, wj, off);
                    if (od < wd || (od == wd && oj < wj)) { wd = od; wj = oj; }
                }
                if (wd == cd && wj == cj) ptr++;
                if (lane == 0) { md[wid * KNN + k] = wd; mj[wid * KNN + k] = wj; }
            }
        }
        __syncthreads();

        if (wid == 0) {
            float fd[4]; int fj[4];
            int base = (lane >> 2) * KNN + (lane & 3) * 4;
#pragma unroll
            for (int t = 0; t < 4; t++) { fd[t] = md[base + t]; fj[t] = mj[base + t]; }
            int ptr = 0;
            for (int k = 0; k < KNN; k++) {
                float cd = (ptr < 4) ? fd[ptr] : __int_as_float(0x7f800000);
                int   cj = (ptr < 4) ? fj[ptr] : 0x7fffffff;
                float wd = cd; int wj = cj;
#pragma unroll
                for (int off = 16; off > 0; off >>= 1) {
                    float od = __shfl_xor_sync(0xffffffffu, wd, off);
                    int   oj = __shfl_xor_sync(0xffffffffu, wj, off);
                    if (od < wd || (od == wd && oj < wj)) { wd = od; wj = oj; }
                }
                if (wd == cd && wj == cj) ptr++;
                if (lane == 0) g_idx[q * KNN + k] = wj;
            }
        }
        __syncthreads();
    }
}

// ---------------------------------------------------------------------------
// GEMM: z[b][n][o] = sum_c W[o][c] * x[b][c][n]; zeroes worklist counter.
// ---------------------------------------------------------------------------
__global__ void __launch_bounds__(128) gemm_kernel(const float* __restrict__ x,
                                                   const float* __restrict__ W) {
    if (blockIdx.x == 0 && threadIdx.x == 0) g_wcount = 0;

    __shared__ float ws[COUT * CIN];
    int tid = threadIdx.x;
#pragma unroll
    for (int u = 0; u < 8; u++)
        ((float4*)ws)[tid + u * 128] = ((const float4*)W)[tid + u * 128];
    __syncthreads();

    int b     = blockIdx.x >> 7;
    int ntile = (blockIdx.x & 127) * 64;
    int nl    = tid & 63;
    int o0    = (tid >> 6) * 32;
    int n     = ntile + nl;

    const float* xb = x + b * CIN * NPTS;

    float acc[32];
#pragma unroll
    for (int i = 0; i < 32; i++) acc[i] = 0.0f;

    for (int c = 0; c < CIN; c += 4) {
        float xv0 = xb[(c + 0) * NPTS + n];
        float xv1 = xb[(c + 1) * NPTS + n];
        float xv2 = xb[(c + 2) * NPTS + n];
        float xv3 = xb[(c + 3) * NPTS + n];
#pragma unroll
        for (int i = 0; i < 32; i++) {
            float4 w4 = *(const float4*)&ws[(o0 + i) * CIN + c];
            acc[i] = fmaf(w4.x, xv0, acc[i]);
            acc[i] = fmaf(w4.y, xv1, acc[i]);
            acc[i] = fmaf(w4.z, xv2, acc[i]);
            acc[i] = fmaf(w4.w, xv3, acc[i]);
        }
    }

    float* zp = g_z + ((size_t)b * NPTS + n) * COUT + o0;
#pragma unroll
    for (int i = 0; i < 32; i += 4)
        *(float4*)&zp[i] = make_float4(acc[i], acc[i + 1], acc[i + 2], acc[i + 3]);
}

// ---------------------------------------------------------------------------
// Max-gather + coords passthrough (tail blocks).
// ---------------------------------------------------------------------------
#define MG_BLOCKS   (BB * 256)
#define CP_FLOAT4   (BB * 3 * NPTS / 4)
#define CP_BLOCKS   (CP_FLOAT4 / 256)

__global__ void __launch_bounds__(256) maxgather_kernel(float* __restrict__ y,
                                                        const float* __restrict__ coords) {
    if (blockIdx.x >= MG_BLOCKS) {
        int i = (blockIdx.x - MG_BLOCKS) * 256 + threadIdx.x;
        float4* dst = (float4*)(y + (size_t)BB * COUT * NPTS);
        dst[i] = ((const float4*)coords)[i];
        return;
    }

    __shared__ float yt[COUT][33];

    int tid = threadIdx.x;
    int w   = tid >> 5;
    int l   = tid & 31;
    int b     = blockIdx.x >> 8;
    int ntile = (blockIdx.x & 255) * 32;

    const float* zb = g_z + (size_t)b * NPTS * COUT;
    const float NEG_INF = __int_as_float(0xff800000);

    for (int qq = 0; qq < 4; qq++) {
        int nl = w * 4 + qq;
        int n  = ntile + nl;
        const int* ip = g_idx + ((size_t)b * NPTS + n) * KNN;
        float m0 = NEG_INF, m1 = NEG_INF;
#pragma unroll
        for (int k = 0; k < KNN; k++) {
            int r = __ldg(&ip[k]);
            const float* zr = zb + (size_t)r * COUT;
            m0 = fmaxf(m0, zr[l]);
            m1 = fmaxf(m1, zr[l + 32]);
        }
        yt[l][nl]      = m0;
        yt[l + 32][nl] = m1;
    }
    __syncthreads();

#pragma unroll
    for (int e = tid; e < COUT * 32; e += 256) {
        int o  = e >> 5;
        int nl = e & 31;
        y[((size_t)b * COUT + o) * NPTS + ntile + nl] = yt[o][nl];
    }
}

// ---------------------------------------------------------------------------
extern "C" void kernel_launch(void* const* d_in, const int* in_sizes, int n_in,
                              void* d_out, int out_size) {
    const float* x      = (const float*)d_in[0];
    const float* coords = (const float*)d_in[1];
    const float* W      = (const float*)d_in[2];
    float*       out    = (float*)d_out;

    gemm_kernel<<<BB * 128, 128>>>(x, W);
    knn_collect<<<NQ / QPB, 256>>>(coords);
    knn_fallback<<<64, 256>>>(coords);
    maxgather_kernel<<<MG_BLOCKS + CP_BLOCKS, 256>>>(out, coords);
}